// round 16
// baseline (speedup 1.0000x reference)
#include <cuda_runtime.h>
#include <cuda_bf16.h>
#include <cstdint>

#define B_  64
#define N_  16
#define T_  128
#define I_  256
#define H_  256
#define G3  768    // 3*H

// Scratch: input projection IH[n][t][b][g] (bih folded in), fp32.
__device__ float g_IH[(size_t)N_ * T_ * B_ * G3];
// hi/lo bf16 copies of x and wih (phase 1).
__device__ __nv_bfloat16 g_xhi[(size_t)B_ * N_ * T_ * I_];
__device__ __nv_bfloat16 g_xlo[(size_t)B_ * N_ * T_ * I_];
__device__ __nv_bfloat16 g_whi[(size_t)N_ * G3 * I_];
__device__ __nv_bfloat16 g_wlo[(size_t)N_ * G3 * I_];
// Double-buffered hidden state as hi/lo bf16 pairs: [2][n][b][k].
__device__ __nv_bfloat16 g_hhi[2 * N_ * B_ * H_];
__device__ __nv_bfloat16 g_hlo[2 * N_ * B_ * H_];

// ---------------------------------------------------------------------------
__global__ void zero_kernel() {
    int i = blockIdx.x * blockDim.x + threadIdx.x;
    if (i < 65536) {
        ((uint4*)g_hhi)[i] = make_uint4(0, 0, 0, 0);
        ((uint4*)g_hlo)[i] = make_uint4(0, 0, 0, 0);
    }
}

// ---------------------------------------------------------------------------
// fp32 -> (hi, lo) bf16 split, writing directly to device globals.
// ---------------------------------------------------------------------------
__global__ void cvt_hilo_kernel(const float* __restrict__ src,
                                int which, size_t n4) {
    __nv_bfloat16* hi = which ? g_whi : g_xhi;
    __nv_bfloat16* lo = which ? g_wlo : g_xlo;
    for (size_t i = blockIdx.x * (size_t)blockDim.x + threadIdx.x; i < n4;
         i += (size_t)gridDim.x * blockDim.x) {
        float4 v = ((const float4*)src)[i];
        float vv[4] = {v.x, v.y, v.z, v.w};
        uint16_t hw[4], lw[4];
#pragma unroll
        for (int u = 0; u < 4; u++) {
            __nv_bfloat16 h = __float2bfloat16_rn(vv[u]);
            float r = vv[u] - __bfloat162float(h);
            __nv_bfloat16 l = __float2bfloat16_rn(r);
            hw[u] = __bfloat16_as_ushort(h);
            lw[u] = __bfloat16_as_ushort(l);
        }
        uint2 ho, lo2;
        ho.x  = (uint32_t)hw[0] | ((uint32_t)hw[1] << 16);
        ho.y  = (uint32_t)hw[2] | ((uint32_t)hw[3] << 16);
        lo2.x = (uint32_t)lw[0] | ((uint32_t)lw[1] << 16);
        lo2.y = (uint32_t)lw[2] | ((uint32_t)lw[3] << 16);
        ((uint2*)hi)[i] = ho;
        ((uint2*)lo)[i] = lo2;
    }
}

// ---------------------------------------------------------------------------
// mma.sync m16n8k16 bf16 + ldmatrix helpers (compute_100-legal).
// ---------------------------------------------------------------------------
__device__ __forceinline__ void mma16816(float* c, const uint32_t* a,
                                         const uint32_t* b) {
    asm volatile(
        "mma.sync.aligned.m16n8k16.row.col.f32.bf16.bf16.f32 "
        "{%0,%1,%2,%3}, {%4,%5,%6,%7}, {%8,%9}, {%0,%1,%2,%3};"
        : "+f"(c[0]), "+f"(c[1]), "+f"(c[2]), "+f"(c[3])
        : "r"(a[0]), "r"(a[1]), "r"(a[2]), "r"(a[3]), "r"(b[0]), "r"(b[1]));
}
__device__ __forceinline__ void ldsm_x4(uint32_t& r0, uint32_t& r1,
                                        uint32_t& r2, uint32_t& r3,
                                        uint32_t addr) {
    asm volatile("ldmatrix.sync.aligned.m8n8.x4.shared.b16 {%0,%1,%2,%3}, [%4];"
                 : "=r"(r0), "=r"(r1), "=r"(r2), "=r"(r3) : "r"(addr));
}
__device__ __forceinline__ uint32_t sm_u32(const void* p) {
    return (uint32_t)__cvta_generic_to_shared(p);
}

// ============================ PHASE 1 (unchanged, validated) ================
#define KT   64
#define SROW 72
#define TILE_ELE (128 * SROW)

__global__ void __launch_bounds__(256, 2)
ih_mma_kernel(const float* __restrict__ bih) {
    extern __shared__ __nv_bfloat16 smem[];
    __nv_bfloat16* SAH = smem;
    __nv_bfloat16* SAL = smem + TILE_ELE;
    __nv_bfloat16* SBH = smem + 2 * TILE_ELE;
    __nv_bfloat16* SBL = smem + 3 * TILE_ELE;

    const int mt  = blockIdx.x;
    const int gt  = blockIdx.y;
    const int n   = blockIdx.z;
    const int tid = threadIdx.x;
    const int wid = tid >> 5;
    const int lane = tid & 31;
    const int wm  = wid & 1;
    const int wn  = wid >> 1;
    const int g   = lane >> 2;
    const int tig = lane & 3;

    const __nv_bfloat16* axh = g_xhi + ((size_t)(mt * N_ + n)) * T_ * I_;
    const __nv_bfloat16* axl = g_xlo + ((size_t)(mt * N_ + n)) * T_ * I_;
    const __nv_bfloat16* bwh = g_whi + ((size_t)(n * G3 + gt * 128)) * I_;
    const __nv_bfloat16* bwl = g_wlo + ((size_t)(n * G3 + gt * 128)) * I_;

    const int arow  = wm * 64 + (lane & 15);
    const int akoff = (lane >> 4) * 8;
    uint32_t aAH[4], aAL[4];
#pragma unroll
    for (int mi = 0; mi < 4; mi++) {
        aAH[mi] = sm_u32(SAH + (arow + mi * 16) * SROW + akoff);
        aAL[mi] = sm_u32(SAL + (arow + mi * 16) * SROW + akoff);
    }
    const int bkoff = ((lane >> 3) & 1) * 8;
    const int bhalf = lane >> 4;
    const int brow  = lane & 7;
    const int nb0 = wn * 32 + brow;
    uint32_t aB01h = sm_u32(SBH + (nb0 + (bhalf ? 8 : 0)) * SROW + bkoff);
    uint32_t aB23h = sm_u32(SBH + (nb0 + (bhalf ? 24 : 16)) * SROW + bkoff);
    uint32_t aB01l = sm_u32(SBL + (nb0 + (bhalf ? 8 : 0)) * SROW + bkoff);
    uint32_t aB23l = sm_u32(SBL + (nb0 + (bhalf ? 24 : 16)) * SROW + bkoff);

    float acc[4][4][4];
#pragma unroll
    for (int mi = 0; mi < 4; mi++)
#pragma unroll
        for (int ni = 0; ni < 4; ni++)
#pragma unroll
            for (int u = 0; u < 4; u++) acc[mi][ni][u] = 0.0f;

    for (int kt = 0; kt < I_; kt += KT) {
#pragma unroll
        for (int l = 0; l < 4; l++) {
            int it = tid + (l << 8);
            int r = it >> 3;
            int q = it & 7;
            size_t goff = (size_t)r * I_ + kt + q * 8;
            int soff = r * SROW + q * 8;
            *(uint4*)(SAH + soff) = *(const uint4*)(axh + goff);
            *(uint4*)(SAL + soff) = *(const uint4*)(axl + goff);
            *(uint4*)(SBH + soff) = *(const uint4*)(bwh + goff);
            *(uint4*)(SBL + soff) = *(const uint4*)(bwl + goff);
        }
        __syncthreads();

#pragma unroll
        for (int kk = 0; kk < KT; kk += 16) {
            const uint32_t off = kk * 2;
            uint32_t af[4][4], bh[4][2], bl[4][2];
#pragma unroll
            for (int mi = 0; mi < 4; mi++)
                ldsm_x4(af[mi][0], af[mi][1], af[mi][2], af[mi][3], aAH[mi] + off);
            ldsm_x4(bh[0][0], bh[0][1], bh[1][0], bh[1][1], aB01h + off);
            ldsm_x4(bh[2][0], bh[2][1], bh[3][0], bh[3][1], aB23h + off);
            ldsm_x4(bl[0][0], bl[0][1], bl[1][0], bl[1][1], aB01l + off);
            ldsm_x4(bl[2][0], bl[2][1], bl[3][0], bl[3][1], aB23l + off);
#pragma unroll
            for (int mi = 0; mi < 4; mi++)
#pragma unroll
                for (int ni = 0; ni < 4; ni++) {
                    mma16816(acc[mi][ni], af[mi], bh[ni]);
                    mma16816(acc[mi][ni], af[mi], bl[ni]);
                }
#pragma unroll
            for (int mi = 0; mi < 4; mi++)
                ldsm_x4(af[mi][0], af[mi][1], af[mi][2], af[mi][3], aAL[mi] + off);
#pragma unroll
            for (int mi = 0; mi < 4; mi++)
#pragma unroll
                for (int ni = 0; ni < 4; ni++)
                    mma16816(acc[mi][ni], af[mi], bh[ni]);
        }
        __syncthreads();
    }

#pragma unroll
    for (int ni = 0; ni < 4; ni++) {
        const int col = gt * 128 + wn * 32 + ni * 8 + 2 * tig;
        const float2 bias = *(const float2*)(bih + n * G3 + col);
#pragma unroll
        for (int mi = 0; mi < 4; mi++) {
            int row = wm * 64 + mi * 16 + g;
            float2 o0, o1;
            o0.x = acc[mi][ni][0] + bias.x;
            o0.y = acc[mi][ni][1] + bias.y;
            o1.x = acc[mi][ni][2] + bias.x;
            o1.y = acc[mi][ni][3] + bias.y;
            *(float2*)(g_IH + (((size_t)(n * T_ + row)) * B_ + mt) * G3 + col) = o0;
            *(float2*)(g_IH + (((size_t)(n * T_ + row + 8)) * B_ + mt) * G3 + col) = o1;
        }
    }
}

// ============================ PHASE 2 =======================================
// R14 change: the 8 CTAs sharing an n form a thread-block cluster; the
// per-step inter-CTA sync is the HW cluster barrier (release/acquire at
// cluster scope orders the h gmem stores) instead of threadfence + gmem
// atomic + L2 polling spin.
// ---------------------------------------------------------------------------
#define WPAD 264

__global__ void __launch_bounds__(256, 1) __cluster_dims__(8, 1, 1)
gru_mma_kernel(const float* __restrict__ whh,
               const float* __restrict__ bhh,
               float* __restrict__ out) {
    extern __shared__ __nv_bfloat16 sm2[];
    __nv_bfloat16* wsh = sm2;                 // [96][WPAD]
    __nv_bfloat16* wsl = wsh + 96 * WPAD;
    __nv_bfloat16* hsh = wsl + 96 * WPAD;     // [64][WPAD]
    __nv_bfloat16* hsl = hsh + 64 * WPAD;

    const int n    = blockIdx.y;
    const int jc   = blockIdx.x;
    const int tid  = threadIdx.x;
    const int wid  = tid >> 5;
    const int lane = tid & 31;
    const int wm   = wid & 1;
    const int wn   = wid >> 1;
    const int tig  = lane & 3;
    const int g8   = lane >> 2;

    // Convert Whh slice fp32 -> hi/lo bf16 smem (once).
    for (int it = tid; it < 96 * 64; it += 256) {
        int row  = it >> 6;
        int q    = it & 63;
        int gate = row >> 5;
        int jl   = row & 31;
        const float4 wv = *(const float4*)(whh +
            ((size_t)(n * G3 + gate * H_ + jc * 32 + jl)) * H_ + q * 4);
        float v[4] = {wv.x, wv.y, wv.z, wv.w};
        uint32_t hw[2], lw[2];
#pragma unroll
        for (int u = 0; u < 2; u++) {
            __nv_bfloat16 h0 = __float2bfloat16_rn(v[2 * u]);
            __nv_bfloat16 h1 = __float2bfloat16_rn(v[2 * u + 1]);
            float r0 = v[2 * u]     - __bfloat162float(h0);
            float r1 = v[2 * u + 1] - __bfloat162float(h1);
            hw[u] = (uint32_t)__bfloat16_as_ushort(h0) |
                    ((uint32_t)__bfloat16_as_ushort(h1) << 16);
            lw[u] = (uint32_t)__bfloat16_as_ushort(__float2bfloat16_rn(r0)) |
                    ((uint32_t)__bfloat16_as_ushort(__float2bfloat16_rn(r1)) << 16);
        }
        *(uint2*)(wsh + row * WPAD + q * 4) = make_uint2(hw[0], hw[1]);
        *(uint2*)(wsl + row * WPAD + q * 4) = make_uint2(lw[0], lw[1]);
    }

    // ldmatrix lane bases.
    const int arow  = wm * 32 + (lane & 15);
    const int akoff = (lane >> 4) * 8;
    uint32_t aAh[2], aAl[2];
#pragma unroll
    for (int mi = 0; mi < 2; mi++) {
        aAh[mi] = sm_u32(hsh + (arow + mi * 16) * WPAD + akoff);
        aAl[mi] = sm_u32(hsl + (arow + mi * 16) * WPAD + akoff);
    }
    const int bkoff = ((lane >> 3) & 1) * 8;
    const int bhalf = lane >> 4;
    const int brow  = wn * 8 + (lane & 7);
    uint32_t aBP0 = sm_u32(wsh + (brow + (bhalf ? 32 : 0)) * WPAD + bkoff);
    uint32_t aBP1 = bhalf ? sm_u32(wsl + brow * WPAD + bkoff)
                          : sm_u32(wsh + (brow + 64) * WPAD + bkoff);
    uint32_t aBP2 = sm_u32(wsl + (brow + (bhalf ? 64 : 32)) * WPAD + bkoff);

    const int jg0 = jc * 32 + wn * 8 + 2 * tig;
    const float2 bhr2 = *(const float2*)(bhh + n * G3 + jg0);
    const float2 bhz2 = *(const float2*)(bhh + n * G3 + H_ + jg0);
    const float2 bhn2 = *(const float2*)(bhh + n * G3 + 2 * H_ + jg0);

    // h_prev carried in registers: idx = mi*2 + rr -> (b, jg0..jg0+1).
    float2 hpr[4];
#pragma unroll
    for (int i = 0; i < 4; i++) { hpr[i].x = 0.0f; hpr[i].y = 0.0f; }

    // All CTAs of the cluster must pass init before step 0's h reads.
    asm volatile("barrier.cluster.arrive.aligned;" ::: "memory");
    asm volatile("barrier.cluster.wait.aligned;" ::: "memory");

    for (int t = 0; t < T_; t++) {
        // Stage h (hi/lo bf16) from gmem (L2-coherent loads).
        const __nv_bfloat16* hhsrc = g_hhi + ((size_t)((t & 1) * N_ + n)) * B_ * H_;
        const __nv_bfloat16* hlsrc = g_hlo + ((size_t)((t & 1) * N_ + n)) * B_ * H_;
        for (int it = tid; it < 2048; it += 256) {
            int r = it >> 5, q = it & 31;
            *(uint4*)(hsh + r * WPAD + q * 8) =
                __ldcg((const uint4*)(hhsrc + r * H_ + q * 8));
            *(uint4*)(hsl + r * WPAD + q * 8) =
                __ldcg((const uint4*)(hlsrc + r * H_ + q * 8));
        }

        // Prefetch IH gate inputs (independent of h) into registers.
        const float* ihb = g_IH + ((size_t)(n * T_ + t) * B_) * G3;
        float2 pir[4], piz[4], pin[4];
#pragma unroll
        for (int mi = 0; mi < 2; mi++)
#pragma unroll
            for (int rr = 0; rr < 2; rr++) {
                const int b = wm * 32 + mi * 16 + g8 + rr * 8;
                const int idx = mi * 2 + rr;
                pir[idx] = *(const float2*)(ihb + (size_t)b * G3 + jg0);
                piz[idx] = *(const float2*)(ihb + (size_t)b * G3 + H_ + jg0);
                pin[idx] = *(const float2*)(ihb + (size_t)b * G3 + 2 * H_ + jg0);
            }
        __syncthreads();

        float acc[2][3][4];
#pragma unroll
        for (int mi = 0; mi < 2; mi++)
#pragma unroll
            for (int ni = 0; ni < 3; ni++)
#pragma unroll
                for (int u = 0; u < 4; u++) acc[mi][ni][u] = 0.0f;

#pragma unroll
        for (int kk = 0; kk < H_; kk += 16) {
            const uint32_t off = kk * 2;
            uint32_t ah[2][4], al[2][4], bh[3][2], bl[3][2];
#pragma unroll
            for (int mi = 0; mi < 2; mi++) {
                ldsm_x4(ah[mi][0], ah[mi][1], ah[mi][2], ah[mi][3], aAh[mi] + off);
                ldsm_x4(al[mi][0], al[mi][1], al[mi][2], al[mi][3], aAl[mi] + off);
            }
            ldsm_x4(bh[0][0], bh[0][1], bh[1][0], bh[1][1], aBP0 + off);
            ldsm_x4(bh[2][0], bh[2][1], bl[0][0], bl[0][1], aBP1 + off);
            ldsm_x4(bl[1][0], bl[1][1], bl[2][0], bl[2][1], aBP2 + off);
#pragma unroll
            for (int mi = 0; mi < 2; mi++)
#pragma unroll
                for (int ni = 0; ni < 3; ni++) {
                    mma16816(acc[mi][ni], ah[mi], bh[ni]);
                    mma16816(acc[mi][ni], ah[mi], bl[ni]);
                    mma16816(acc[mi][ni], al[mi], bh[ni]);
                }
        }

        // Fused gate epilogue (h_prev and IH already in registers).
        const int buf = (t + 1) & 1;
        __nv_bfloat16* hhdst = g_hhi + ((size_t)(buf * N_ + n)) * B_ * H_;
        __nv_bfloat16* hldst = g_hlo + ((size_t)(buf * N_ + n)) * B_ * H_;

#pragma unroll
        for (int mi = 0; mi < 2; mi++)
#pragma unroll
            for (int rr = 0; rr < 2; rr++) {
                const int b   = wm * 32 + mi * 16 + g8 + rr * 8;
                const int ci  = rr * 2;
                const int idx = mi * 2 + rr;
                float hr0 = acc[mi][0][ci]     + bhr2.x;
                float hr1 = acc[mi][0][ci + 1] + bhr2.y;
                float hz0 = acc[mi][1][ci]     + bhz2.x;
                float hz1 = acc[mi][1][ci + 1] + bhz2.y;
                float hn0 = acc[mi][2][ci]     + bhn2.x;
                float hn1 = acc[mi][2][ci + 1] + bhn2.y;
                float rg0 = 1.0f / (1.0f + __expf(-(pir[idx].x + hr0)));
                float rg1 = 1.0f / (1.0f + __expf(-(pir[idx].y + hr1)));
                float zg0 = 1.0f / (1.0f + __expf(-(piz[idx].x + hz0)));
                float zg1 = 1.0f / (1.0f + __expf(-(piz[idx].y + hz1)));
                float ng0 = tanhf(pin[idx].x + rg0 * hn0);
                float ng1 = tanhf(pin[idx].y + rg1 * hn1);
                float h0 = (1.0f - zg0) * ng0 + zg0 * hpr[idx].x;
                float h1 = (1.0f - zg1) * ng1 + zg1 * hpr[idx].y;
                hpr[idx].x = h0;
                hpr[idx].y = h1;

                float2 o; o.x = h0; o.y = h1;
                *(float2*)(out + ((size_t)(b * N_ + n) * T_ + t) * H_ + jg0) = o;

                __nv_bfloat16 hi0 = __float2bfloat16_rn(h0);
                __nv_bfloat16 hi1 = __float2bfloat16_rn(h1);
                __nv_bfloat16 lo0 = __float2bfloat16_rn(h0 - __bfloat162float(hi0));
                __nv_bfloat16 lo1 = __float2bfloat16_rn(h1 - __bfloat162float(hi1));
                *(uint32_t*)(hhdst + (size_t)b * H_ + jg0) =
                    (uint32_t)__bfloat16_as_ushort(hi0) |
                    ((uint32_t)__bfloat16_as_ushort(hi1) << 16);
                *(uint32_t*)(hldst + (size_t)b * H_ + jg0) =
                    (uint32_t)__bfloat16_as_ushort(lo0) |
                    ((uint32_t)__bfloat16_as_ushort(lo1) << 16);
            }

        // Cluster barrier: arrive releases the h stores (cluster scope),
        // wait acquires peers' stores. Replaces threadfence+atomic+spin.
        asm volatile("barrier.cluster.arrive.aligned;" ::: "memory");
        asm volatile("barrier.cluster.wait.aligned;" ::: "memory");
    }
}

// ---------------------------------------------------------------------------
extern "C" void kernel_launch(void* const* d_in, const int* in_sizes, int n_in,
                              void* d_out, int out_size) {
    const float* x   = (const float*)d_in[0];
    const float* wih = (const float*)d_in[1];
    const float* whh = (const float*)d_in[2];
    const float* bih = (const float*)d_in[3];
    const float* bhh = (const float*)d_in[4];
    float* out = (float*)d_out;

    const int smem1 = 4 * TILE_ELE * (int)sizeof(__nv_bfloat16);       // 73,728 B
    const int smem2 = (2 * 96 * WPAD + 2 * 64 * WPAD) *
                      (int)sizeof(__nv_bfloat16);                      // 168,960 B
    cudaFuncSetAttribute(ih_mma_kernel,
                         cudaFuncAttributeMaxDynamicSharedMemorySize, smem1);
    cudaFuncSetAttribute(gru_mma_kernel,
                         cudaFuncAttributeMaxDynamicSharedMemorySize, smem2);

    zero_kernel<<<256, 256>>>();

    const size_t nx4 = (size_t)B_ * N_ * T_ * I_ / 4;
    const size_t nw4 = (size_t)N_ * G3 * I_ / 4;
    cvt_hilo_kernel<<<4096, 256>>>(x, 0, nx4);
    cvt_hilo_kernel<<<1024, 256>>>(wih, 1, nw4);

    ih_mma_kernel<<<dim3(64, 6, 16), 256, smem1>>>(bih);
    gru_mma_kernel<<<dim3(8, 16), 256, smem2>>>(whh, bhh, out);
}

// round 17
// speedup vs baseline: 1.4843x; 1.4843x over previous
#include <cuda_runtime.h>
#include <cuda_bf16.h>
#include <cstdint>

#define B_  64
#define N_  16
#define T_  128
#define I_  256
#define H_  256
#define G3  768    // 3*H

// Scratch: input projection IH[n][t][b][g] (bih folded in), fp32.
__device__ float g_IH[(size_t)N_ * T_ * B_ * G3];
// hi/lo bf16 copies of x and wih (phase 1).
__device__ __nv_bfloat16 g_xhi[(size_t)B_ * N_ * T_ * I_];
__device__ __nv_bfloat16 g_xlo[(size_t)B_ * N_ * T_ * I_];
__device__ __nv_bfloat16 g_whi[(size_t)N_ * G3 * I_];
__device__ __nv_bfloat16 g_wlo[(size_t)N_ * G3 * I_];
// Double-buffered hidden state as hi/lo bf16 pairs: [2][n][b][k].
__device__ __nv_bfloat16 g_hhi[2 * N_ * B_ * H_];
__device__ __nv_bfloat16 g_hlo[2 * N_ * B_ * H_];
// Per-n software barriers (8 CTAs each), reset per launch by zero_kernel.
__device__ int g_bar_cnt[N_];
__device__ int g_bar_gen[N_];

// ---------------------------------------------------------------------------
__global__ void zero_kernel() {
    int i = blockIdx.x * blockDim.x + threadIdx.x;
    if (i < 65536) {
        ((uint4*)g_hhi)[i] = make_uint4(0, 0, 0, 0);
        ((uint4*)g_hlo)[i] = make_uint4(0, 0, 0, 0);
    }
    if (i < N_) { g_bar_cnt[i] = 0; g_bar_gen[i] = 0; }
}

// ---------------------------------------------------------------------------
// fp32 -> (hi, lo) bf16 split, writing directly to device globals.
// ---------------------------------------------------------------------------
__global__ void cvt_hilo_kernel(const float* __restrict__ src,
                                int which, size_t n4) {
    __nv_bfloat16* hi = which ? g_whi : g_xhi;
    __nv_bfloat16* lo = which ? g_wlo : g_xlo;
    for (size_t i = blockIdx.x * (size_t)blockDim.x + threadIdx.x; i < n4;
         i += (size_t)gridDim.x * blockDim.x) {
        float4 v = ((const float4*)src)[i];
        float vv[4] = {v.x, v.y, v.z, v.w};
        uint16_t hw[4], lw[4];
#pragma unroll
        for (int u = 0; u < 4; u++) {
            __nv_bfloat16 h = __float2bfloat16_rn(vv[u]);
            float r = vv[u] - __bfloat162float(h);
            __nv_bfloat16 l = __float2bfloat16_rn(r);
            hw[u] = __bfloat16_as_ushort(h);
            lw[u] = __bfloat16_as_ushort(l);
        }
        uint2 ho, lo2;
        ho.x  = (uint32_t)hw[0] | ((uint32_t)hw[1] << 16);
        ho.y  = (uint32_t)hw[2] | ((uint32_t)hw[3] << 16);
        lo2.x = (uint32_t)lw[0] | ((uint32_t)lw[1] << 16);
        lo2.y = (uint32_t)lw[2] | ((uint32_t)lw[3] << 16);
        ((uint2*)hi)[i] = ho;
        ((uint2*)lo)[i] = lo2;
    }
}

// ---------------------------------------------------------------------------
// mma.sync m16n8k16 bf16 + ldmatrix helpers (compute_100-legal).
// ---------------------------------------------------------------------------
__device__ __forceinline__ void mma16816(float* c, const uint32_t* a,
                                         const uint32_t* b) {
    asm volatile(
        "mma.sync.aligned.m16n8k16.row.col.f32.bf16.bf16.f32 "
        "{%0,%1,%2,%3}, {%4,%5,%6,%7}, {%8,%9}, {%0,%1,%2,%3};"
        : "+f"(c[0]), "+f"(c[1]), "+f"(c[2]), "+f"(c[3])
        : "r"(a[0]), "r"(a[1]), "r"(a[2]), "r"(a[3]), "r"(b[0]), "r"(b[1]));
}
__device__ __forceinline__ void ldsm_x4(uint32_t& r0, uint32_t& r1,
                                        uint32_t& r2, uint32_t& r3,
                                        uint32_t addr) {
    asm volatile("ldmatrix.sync.aligned.m8n8.x4.shared.b16 {%0,%1,%2,%3}, [%4];"
                 : "=r"(r0), "=r"(r1), "=r"(r2), "=r"(r3) : "r"(addr));
}
__device__ __forceinline__ uint32_t sm_u32(const void* p) {
    return (uint32_t)__cvta_generic_to_shared(p);
}

// ============================ PHASE 1 (unchanged, validated) ================
#define KT   64
#define SROW 72
#define TILE_ELE (128 * SROW)

__global__ void __launch_bounds__(256, 2)
ih_mma_kernel(const float* __restrict__ bih) {
    extern __shared__ __nv_bfloat16 smem[];
    __nv_bfloat16* SAH = smem;
    __nv_bfloat16* SAL = smem + TILE_ELE;
    __nv_bfloat16* SBH = smem + 2 * TILE_ELE;
    __nv_bfloat16* SBL = smem + 3 * TILE_ELE;

    const int mt  = blockIdx.x;
    const int gt  = blockIdx.y;
    const int n   = blockIdx.z;
    const int tid = threadIdx.x;
    const int wid = tid >> 5;
    const int lane = tid & 31;
    const int wm  = wid & 1;
    const int wn  = wid >> 1;
    const int g   = lane >> 2;
    const int tig = lane & 3;

    const __nv_bfloat16* axh = g_xhi + ((size_t)(mt * N_ + n)) * T_ * I_;
    const __nv_bfloat16* axl = g_xlo + ((size_t)(mt * N_ + n)) * T_ * I_;
    const __nv_bfloat16* bwh = g_whi + ((size_t)(n * G3 + gt * 128)) * I_;
    const __nv_bfloat16* bwl = g_wlo + ((size_t)(n * G3 + gt * 128)) * I_;

    const int arow  = wm * 64 + (lane & 15);
    const int akoff = (lane >> 4) * 8;
    uint32_t aAH[4], aAL[4];
#pragma unroll
    for (int mi = 0; mi < 4; mi++) {
        aAH[mi] = sm_u32(SAH + (arow + mi * 16) * SROW + akoff);
        aAL[mi] = sm_u32(SAL + (arow + mi * 16) * SROW + akoff);
    }
    const int bkoff = ((lane >> 3) & 1) * 8;
    const int bhalf = lane >> 4;
    const int brow  = lane & 7;
    const int nb0 = wn * 32 + brow;
    uint32_t aB01h = sm_u32(SBH + (nb0 + (bhalf ? 8 : 0)) * SROW + bkoff);
    uint32_t aB23h = sm_u32(SBH + (nb0 + (bhalf ? 24 : 16)) * SROW + bkoff);
    uint32_t aB01l = sm_u32(SBL + (nb0 + (bhalf ? 8 : 0)) * SROW + bkoff);
    uint32_t aB23l = sm_u32(SBL + (nb0 + (bhalf ? 24 : 16)) * SROW + bkoff);

    float acc[4][4][4];
#pragma unroll
    for (int mi = 0; mi < 4; mi++)
#pragma unroll
        for (int ni = 0; ni < 4; ni++)
#pragma unroll
            for (int u = 0; u < 4; u++) acc[mi][ni][u] = 0.0f;

    for (int kt = 0; kt < I_; kt += KT) {
#pragma unroll
        for (int l = 0; l < 4; l++) {
            int it = tid + (l << 8);
            int r = it >> 3;
            int q = it & 7;
            size_t goff = (size_t)r * I_ + kt + q * 8;
            int soff = r * SROW + q * 8;
            *(uint4*)(SAH + soff) = *(const uint4*)(axh + goff);
            *(uint4*)(SAL + soff) = *(const uint4*)(axl + goff);
            *(uint4*)(SBH + soff) = *(const uint4*)(bwh + goff);
            *(uint4*)(SBL + soff) = *(const uint4*)(bwl + goff);
        }
        __syncthreads();

#pragma unroll
        for (int kk = 0; kk < KT; kk += 16) {
            const uint32_t off = kk * 2;
            uint32_t af[4][4], bh[4][2], bl[4][2];
#pragma unroll
            for (int mi = 0; mi < 4; mi++)
                ldsm_x4(af[mi][0], af[mi][1], af[mi][2], af[mi][3], aAH[mi] + off);
            ldsm_x4(bh[0][0], bh[0][1], bh[1][0], bh[1][1], aB01h + off);
            ldsm_x4(bh[2][0], bh[2][1], bh[3][0], bh[3][1], aB23h + off);
            ldsm_x4(bl[0][0], bl[0][1], bl[1][0], bl[1][1], aB01l + off);
            ldsm_x4(bl[2][0], bl[2][1], bl[3][0], bl[3][1], aB23l + off);
#pragma unroll
            for (int mi = 0; mi < 4; mi++)
#pragma unroll
                for (int ni = 0; ni < 4; ni++) {
                    mma16816(acc[mi][ni], af[mi], bh[ni]);
                    mma16816(acc[mi][ni], af[mi], bl[ni]);
                }
#pragma unroll
            for (int mi = 0; mi < 4; mi++)
                ldsm_x4(af[mi][0], af[mi][1], af[mi][2], af[mi][3], aAL[mi] + off);
#pragma unroll
            for (int mi = 0; mi < 4; mi++)
#pragma unroll
                for (int ni = 0; ni < 4; ni++)
                    mma16816(acc[mi][ni], af[mi], bh[ni]);
        }
        __syncthreads();
    }

#pragma unroll
    for (int ni = 0; ni < 4; ni++) {
        const int col = gt * 128 + wn * 32 + ni * 8 + 2 * tig;
        const float2 bias = *(const float2*)(bih + n * G3 + col);
#pragma unroll
        for (int mi = 0; mi < 4; mi++) {
            int row = wm * 64 + mi * 16 + g;
            float2 o0, o1;
            o0.x = acc[mi][ni][0] + bias.x;
            o0.y = acc[mi][ni][1] + bias.y;
            o1.x = acc[mi][ni][2] + bias.x;
            o1.y = acc[mi][ni][3] + bias.y;
            *(float2*)(g_IH + (((size_t)(n * T_ + row)) * B_ + mt) * G3 + col) = o0;
            *(float2*)(g_IH + (((size_t)(n * T_ + row + 8)) * B_ + mt) * G3 + col) = o1;
        }
    }
}

// ============================ PHASE 2 =======================================
// R13 structure (software per-n barrier) + two changes:
//  (a) no all-threads __threadfence: syncthreads (CTA-scope HB) + tid0
//      atom.acq_rel arrive + st.release gen + ld.acquire poll gives the
//      same transitive happens-before at a fraction of the cost.
//  (b) IH prefetch for step t+1 hoisted before the barrier (h-independent),
//      hiding its gmem latency behind the barrier wait.
// ---------------------------------------------------------------------------
#define WPAD 264

__global__ void __launch_bounds__(256, 1)
gru_mma_kernel(const float* __restrict__ whh,
               const float* __restrict__ bhh,
               float* __restrict__ out) {
    extern __shared__ __nv_bfloat16 sm2[];
    __nv_bfloat16* wsh = sm2;                 // [96][WPAD]
    __nv_bfloat16* wsl = wsh + 96 * WPAD;
    __nv_bfloat16* hsh = wsl + 96 * WPAD;     // [64][WPAD]
    __nv_bfloat16* hsl = hsh + 64 * WPAD;

    const int n    = blockIdx.y;
    const int jc   = blockIdx.x;
    const int tid  = threadIdx.x;
    const int wid  = tid >> 5;
    const int lane = tid & 31;
    const int wm   = wid & 1;
    const int wn   = wid >> 1;
    const int tig  = lane & 3;
    const int g8   = lane >> 2;

    // Convert Whh slice fp32 -> hi/lo bf16 smem (once).
    for (int it = tid; it < 96 * 64; it += 256) {
        int row  = it >> 6;
        int q    = it & 63;
        int gate = row >> 5;
        int jl   = row & 31;
        const float4 wv = *(const float4*)(whh +
            ((size_t)(n * G3 + gate * H_ + jc * 32 + jl)) * H_ + q * 4);
        float v[4] = {wv.x, wv.y, wv.z, wv.w};
        uint32_t hw[2], lw[2];
#pragma unroll
        for (int u = 0; u < 2; u++) {
            __nv_bfloat16 h0 = __float2bfloat16_rn(v[2 * u]);
            __nv_bfloat16 h1 = __float2bfloat16_rn(v[2 * u + 1]);
            float r0 = v[2 * u]     - __bfloat162float(h0);
            float r1 = v[2 * u + 1] - __bfloat162float(h1);
            hw[u] = (uint32_t)__bfloat16_as_ushort(h0) |
                    ((uint32_t)__bfloat16_as_ushort(h1) << 16);
            lw[u] = (uint32_t)__bfloat16_as_ushort(__float2bfloat16_rn(r0)) |
                    ((uint32_t)__bfloat16_as_ushort(__float2bfloat16_rn(r1)) << 16);
        }
        *(uint2*)(wsh + row * WPAD + q * 4) = make_uint2(hw[0], hw[1]);
        *(uint2*)(wsl + row * WPAD + q * 4) = make_uint2(lw[0], lw[1]);
    }

    // ldmatrix lane bases.
    const int arow  = wm * 32 + (lane & 15);
    const int akoff = (lane >> 4) * 8;
    uint32_t aAh[2], aAl[2];
#pragma unroll
    for (int mi = 0; mi < 2; mi++) {
        aAh[mi] = sm_u32(hsh + (arow + mi * 16) * WPAD + akoff);
        aAl[mi] = sm_u32(hsl + (arow + mi * 16) * WPAD + akoff);
    }
    const int bkoff = ((lane >> 3) & 1) * 8;
    const int bhalf = lane >> 4;
    const int brow  = wn * 8 + (lane & 7);
    uint32_t aBP0 = sm_u32(wsh + (brow + (bhalf ? 32 : 0)) * WPAD + bkoff);
    uint32_t aBP1 = bhalf ? sm_u32(wsl + brow * WPAD + bkoff)
                          : sm_u32(wsh + (brow + 64) * WPAD + bkoff);
    uint32_t aBP2 = sm_u32(wsl + (brow + (bhalf ? 64 : 32)) * WPAD + bkoff);

    const int jg0 = jc * 32 + wn * 8 + 2 * tig;
    const float2 bhr2 = *(const float2*)(bhh + n * G3 + jg0);
    const float2 bhz2 = *(const float2*)(bhh + n * G3 + H_ + jg0);
    const float2 bhn2 = *(const float2*)(bhh + n * G3 + 2 * H_ + jg0);

    // Per-thread IH row offsets (constant across steps).
    size_t ihoff[4];
#pragma unroll
    for (int mi = 0; mi < 2; mi++)
#pragma unroll
        for (int rr = 0; rr < 2; rr++) {
            const int b = wm * 32 + mi * 16 + g8 + rr * 8;
            ihoff[mi * 2 + rr] = (size_t)b * G3 + jg0;
        }

    // h_prev carried in registers: idx = mi*2 + rr -> (b, jg0..jg0+1).
    float2 hpr[4];
#pragma unroll
    for (int i = 0; i < 4; i++) { hpr[i].x = 0.0f; hpr[i].y = 0.0f; }

    // Prefetch IH gate inputs for t=0.
    float2 pir[4], piz[4], pin[4];
    {
        const float* ihb = g_IH + ((size_t)(n * T_ + 0) * B_) * G3;
#pragma unroll
        for (int idx = 0; idx < 4; idx++) {
            pir[idx] = *(const float2*)(ihb + ihoff[idx]);
            piz[idx] = *(const float2*)(ihb + ihoff[idx] + H_);
            pin[idx] = *(const float2*)(ihb + ihoff[idx] + 2 * H_);
        }
    }

    for (int t = 0; t < T_; t++) {
        // Stage h (hi/lo bf16) from gmem (L2-coherent loads).
        const __nv_bfloat16* hhsrc = g_hhi + ((size_t)((t & 1) * N_ + n)) * B_ * H_;
        const __nv_bfloat16* hlsrc = g_hlo + ((size_t)((t & 1) * N_ + n)) * B_ * H_;
        for (int it = tid; it < 2048; it += 256) {
            int r = it >> 5, q = it & 31;
            *(uint4*)(hsh + r * WPAD + q * 8) =
                __ldcg((const uint4*)(hhsrc + r * H_ + q * 8));
            *(uint4*)(hsl + r * WPAD + q * 8) =
                __ldcg((const uint4*)(hlsrc + r * H_ + q * 8));
        }
        __syncthreads();

        float acc[2][3][4];
#pragma unroll
        for (int mi = 0; mi < 2; mi++)
#pragma unroll
            for (int ni = 0; ni < 3; ni++)
#pragma unroll
                for (int u = 0; u < 4; u++) acc[mi][ni][u] = 0.0f;

#pragma unroll
        for (int kk = 0; kk < H_; kk += 16) {
            const uint32_t off = kk * 2;
            uint32_t ah[2][4], al[2][4], bh[3][2], bl[3][2];
#pragma unroll
            for (int mi = 0; mi < 2; mi++) {
                ldsm_x4(ah[mi][0], ah[mi][1], ah[mi][2], ah[mi][3], aAh[mi] + off);
                ldsm_x4(al[mi][0], al[mi][1], al[mi][2], al[mi][3], aAl[mi] + off);
            }
            ldsm_x4(bh[0][0], bh[0][1], bh[1][0], bh[1][1], aBP0 + off);
            ldsm_x4(bh[2][0], bh[2][1], bl[0][0], bl[0][1], aBP1 + off);
            ldsm_x4(bl[1][0], bl[1][1], bl[2][0], bl[2][1], aBP2 + off);
#pragma unroll
            for (int mi = 0; mi < 2; mi++)
#pragma unroll
                for (int ni = 0; ni < 3; ni++) {
                    mma16816(acc[mi][ni], ah[mi], bh[ni]);
                    mma16816(acc[mi][ni], ah[mi], bl[ni]);
                    mma16816(acc[mi][ni], al[mi], bh[ni]);
                }
        }

        // Fused gate epilogue (h_prev and IH already in registers).
        const int buf = (t + 1) & 1;
        __nv_bfloat16* hhdst = g_hhi + ((size_t)(buf * N_ + n)) * B_ * H_;
        __nv_bfloat16* hldst = g_hlo + ((size_t)(buf * N_ + n)) * B_ * H_;

#pragma unroll
        for (int mi = 0; mi < 2; mi++)
#pragma unroll
            for (int rr = 0; rr < 2; rr++) {
                const int b   = wm * 32 + mi * 16 + g8 + rr * 8;
                const int ci  = rr * 2;
                const int idx = mi * 2 + rr;
                float hr0 = acc[mi][0][ci]     + bhr2.x;
                float hr1 = acc[mi][0][ci + 1] + bhr2.y;
                float hz0 = acc[mi][1][ci]     + bhz2.x;
                float hz1 = acc[mi][1][ci + 1] + bhz2.y;
                float hn0 = acc[mi][2][ci]     + bhn2.x;
                float hn1 = acc[mi][2][ci + 1] + bhn2.y;
                float rg0 = 1.0f / (1.0f + __expf(-(pir[idx].x + hr0)));
                float rg1 = 1.0f / (1.0f + __expf(-(pir[idx].y + hr1)));
                float zg0 = 1.0f / (1.0f + __expf(-(piz[idx].x + hz0)));
                float zg1 = 1.0f / (1.0f + __expf(-(piz[idx].y + hz1)));
                float ng0 = tanhf(pin[idx].x + rg0 * hn0);
                float ng1 = tanhf(pin[idx].y + rg1 * hn1);
                float h0 = (1.0f - zg0) * ng0 + zg0 * hpr[idx].x;
                float h1 = (1.0f - zg1) * ng1 + zg1 * hpr[idx].y;
                hpr[idx].x = h0;
                hpr[idx].y = h1;

                float2 o; o.x = h0; o.y = h1;
                *(float2*)(out + ((size_t)(b * N_ + n) * T_ + t) * H_ + jg0) = o;

                __nv_bfloat16 hi0 = __float2bfloat16_rn(h0);
                __nv_bfloat16 hi1 = __float2bfloat16_rn(h1);
                __nv_bfloat16 lo0 = __float2bfloat16_rn(h0 - __bfloat162float(hi0));
                __nv_bfloat16 lo1 = __float2bfloat16_rn(h1 - __bfloat162float(hi1));
                *(uint32_t*)(hhdst + (size_t)b * H_ + jg0) =
                    (uint32_t)__bfloat16_as_ushort(hi0) |
                    ((uint32_t)__bfloat16_as_ushort(hi1) << 16);
                *(uint32_t*)(hldst + (size_t)b * H_ + jg0) =
                    (uint32_t)__bfloat16_as_ushort(lo0) |
                    ((uint32_t)__bfloat16_as_ushort(lo1) << 16);
            }

        // Prefetch IH for step t+1 (h-independent) to hide latency behind
        // the barrier.
        if (t + 1 < T_) {
            const float* ihb = g_IH + ((size_t)(n * T_ + (t + 1)) * B_) * G3;
#pragma unroll
            for (int idx = 0; idx < 4; idx++) {
                pir[idx] = *(const float2*)(ihb + ihoff[idx]);
                piz[idx] = *(const float2*)(ihb + ihoff[idx] + H_);
                pin[idx] = *(const float2*)(ihb + ihoff[idx] + 2 * H_);
            }
        }

        // Per-n barrier: syncthreads gives CTA-scope HB for all epilogue
        // stores; tid0's acq_rel arrive + release gen publish them at gpu
        // scope; pollers acquire gen. No all-threads threadfence needed.
        __syncthreads();
        if (tid == 0) {
            int target = t + 1;
            int old;
            asm volatile("atom.add.acq_rel.gpu.global.u32 %0, [%1], %2;"
                         : "=r"(old) : "l"(&g_bar_cnt[n]), "r"(1u) : "memory");
            if (old == 7) {
                g_bar_cnt[n] = 0;
                asm volatile("st.release.gpu.global.u32 [%0], %1;"
                             :: "l"(&g_bar_gen[n]), "r"(target) : "memory");
            } else {
                int v;
                do {
                    asm volatile("ld.acquire.gpu.global.u32 %0, [%1];"
                                 : "=r"(v) : "l"(&g_bar_gen[n]) : "memory");
                } while (v < target);
            }
        }
        __syncthreads();
    }
}

// ---------------------------------------------------------------------------
extern "C" void kernel_launch(void* const* d_in, const int* in_sizes, int n_in,
                              void* d_out, int out_size) {
    const float* x   = (const float*)d_in[0];
    const float* wih = (const float*)d_in[1];
    const float* whh = (const float*)d_in[2];
    const float* bih = (const float*)d_in[3];
    const float* bhh = (const float*)d_in[4];
    float* out = (float*)d_out;

    const int smem1 = 4 * TILE_ELE * (int)sizeof(__nv_bfloat16);       // 73,728 B
    const int smem2 = (2 * 96 * WPAD + 2 * 64 * WPAD) *
                      (int)sizeof(__nv_bfloat16);                      // 168,960 B
    cudaFuncSetAttribute(ih_mma_kernel,
                         cudaFuncAttributeMaxDynamicSharedMemorySize, smem1);
    cudaFuncSetAttribute(gru_mma_kernel,
                         cudaFuncAttributeMaxDynamicSharedMemorySize, smem2);

    zero_kernel<<<256, 256>>>();

    const size_t nx4 = (size_t)B_ * N_ * T_ * I_ / 4;
    const size_t nw4 = (size_t)N_ * G3 * I_ / 4;
    cvt_hilo_kernel<<<4096, 256>>>(x, 0, nx4);
    cvt_hilo_kernel<<<1024, 256>>>(wih, 1, nw4);

    ih_mma_kernel<<<dim3(64, 6, 16), 256, smem1>>>(bih);
    gru_mma_kernel<<<dim3(8, 16), 256, smem2>>>(whh, bhh, out);
}